// round 17
// baseline (speedup 1.0000x reference)
#include <cuda_runtime.h>
#include <math.h>

#define B_    2
#define L_    4096
#define K_    32
#define HALF_ 128
#define NPAIR 28
#define EPSF  1e-6f
#define TWOPI 6.28318530717958647692f
#define BL_   (B_*L_)
#define NP2   (BL_/2)
#define GRID_ 456

typedef unsigned long long ull;
typedef long long ll;

__device__ float g_wsym[NPAIR*HALF_];   // 2pi*(W[mn]+W[nm])
__device__ float g_wv[3*HALF_];         // 2pi*W_vec
__device__ float g_bias[HALF_];         // 2pi*sqrt(EPS)*sum_diag W
__device__ float g_fr[BL_*16];          // per res: e1 e2 e3 t (float4 each), masked

__constant__ int c_pm[NPAIR] = {0,0,0,0,0,0,0,1,1,1,1,1,1,2,2,2,2,2,3,3,3,3,4,4,4,5,5,6};
__constant__ int c_pn[NPAIR] = {1,2,3,4,5,6,7,2,3,4,5,6,7,3,4,5,6,7,4,5,6,7,5,6,7,6,7,7};

static __device__ __forceinline__ ull pack2(float lo, float hi){
    ull r; asm("mov.b64 %0, {%1,%2};" : "=l"(r) : "f"(lo), "f"(hi)); return r;
}
static __device__ __forceinline__ void unpack2(ull v, float& lo, float& hi){
    asm("mov.b64 {%0,%1}, %2;" : "=f"(lo), "=f"(hi) : "l"(v));
}
static __device__ __forceinline__ ull fma2(ull a, ull b, ull c){
    ull d; asm("fma.rn.f32x2 %0, %1, %2, %3;" : "=l"(d) : "l"(a), "l"(b), "l"(c)); return d;
}
static __device__ __forceinline__ ull mul2(ull a, ull b){
    ull d; asm("mul.rn.f32x2 %0, %1, %2;" : "=l"(d) : "l"(a), "l"(b)); return d;
}
static __device__ __forceinline__ ull dup2(float x){ return pack2(x, x); }

static __device__ __forceinline__ unsigned sa(const void* p){
    return (unsigned)__cvta_generic_to_shared(p);
}
static __device__ __forceinline__ void cp16(unsigned s, const void* g){
    asm volatile("cp.async.ca.shared.global [%0], [%1], 16;" :: "r"(s), "l"(g));
}
static __device__ __forceinline__ void cp8(unsigned s, const void* g){
    asm volatile("cp.async.ca.shared.global [%0], [%1], 8;" :: "r"(s), "l"(g));
}
static __device__ __forceinline__ void cp4(unsigned s, const void* g){
    asm volatile("cp.async.ca.shared.global [%0], [%1], 4;" :: "r"(s), "l"(g));
}

// ---------------------------------------------------------------------------
// Prep: block 0 = W preparation; blocks 1..32 = frames (masked R rows + t).
// ---------------------------------------------------------------------------
__global__ void prep_kernel(const float* __restrict__ X, const void* __restrict__ Cv,
                            const float* __restrict__ Wvec, const float* __restrict__ Wdist){
    if (blockIdx.x == 0){
        int e = threadIdx.x;
        if (e >= 128) return;
        #pragma unroll
        for (int d = 0; d < 3; d++) g_wv[d*HALF_ + e] = TWOPI * Wvec[d*HALF_ + e];
        float b = 0.f;
        #pragma unroll
        for (int m = 0; m < 8; m++) b += Wdist[(m*8+m)*HALF_ + e];
        g_bias[e] = TWOPI * sqrtf(EPSF) * b;
        for (int p = 0; p < NPAIR; p++){
            int m = c_pm[p], n = c_pn[p];
            g_wsym[p*HALF_ + e] = TWOPI * (Wdist[(m*8+n)*HALF_ + e] + Wdist[(n*8+m)*HALF_ + e]);
        }
        return;
    }
    int r = (blockIdx.x - 1)*256 + threadIdx.x;   // 32*256 = 8192
    int4 vc = ((const int4*)Cv)[threadIdx.x & 31];
    int is64C = (__reduce_or_sync(0xffffffffu, vc.y | vc.w) == 0);
    ll cv = is64C ? ((const ll*)Cv)[r] : (ll)((const int*)Cv)[r];
    float mask = (cv > 0) ? 1.f : 0.f;

    const float* x = X + (size_t)r * 12;
    float Nx=x[0], Ny=x[1], Nz=x[2];
    float Ax=x[3], Ay=x[4], Az=x[5];
    float Cx=x[6], Cy=x[7], Cz=x[8];

    float v1x=Nx-Ax, v1y=Ny-Ay, v1z=Nz-Az;
    float n1 = sqrtf(v1x*v1x + v1y*v1y + v1z*v1z) + EPSF;
    float e1x=v1x/n1, e1y=v1y/n1, e1z=v1z/n1;

    float u2x=Cx-Ax, u2y=Cy-Ay, u2z=Cz-Az;
    float n2 = sqrtf(u2x*u2x + u2y*u2y + u2z*u2z) + EPSF;
    u2x/=n2; u2y/=n2; u2z/=n2;

    float dt = u2x*e1x + u2y*e1y + u2z*e1z;
    float w2x = u2x - dt*e1x, w2y = u2y - dt*e1y, w2z = u2z - dt*e1z;
    float n3 = sqrtf(w2x*w2x + w2y*w2y + w2z*w2z) + EPSF;
    float e2x=w2x/n3, e2y=w2y/n3, e2z=w2z/n3;

    float e3x = e1y*e2z - e1z*e2y;
    float e3y = e1z*e2x - e1x*e2z;
    float e3z = e1x*e2y - e1y*e2x;

    float4* g4 = (float4*)g_fr + (size_t)r*4;
    g4[0] = make_float4(mask*e1x, mask*e1y, mask*e1z, 0.f);
    g4[1] = make_float4(mask*e2x, mask*e2y, mask*e2z, 0.f);
    g4[2] = make_float4(mask*e3x, mask*e3y, mask*e3z, 0.f);
    g4[3] = make_float4(mask*Ax,  mask*Ay,  mask*Az,  0.f);
}

// ---------------------------------------------------------------------------
// Persistent main kernel: processes residue PAIRS (2q, 2q+1). The hd hot loop
// reads W once per pair (amortized over 2 residues); 16 f32x2 accumulators.
// ---------------------------------------------------------------------------
__global__ __launch_bounds__(256, 3)
void edge_kernel(const float* __restrict__ X, const void* __restrict__ eidxv,
                 float* __restrict__ out){
    __shared__ __align__(16) float s_wsym[NPAIR*HALF_];    // 14336 B
    __shared__ __align__(16) float s_wv[3*HALF_];          // 1536 B
    __shared__ __align__(16) float s_bias[HALF_];          // 512 B
    __shared__ __align__(16) float s_xj[2][2][K_*12];      // 6144 B
    __shared__ __align__(16) float s_tj[2][2][K_*4];       // 2048 B
    __shared__ __align__(16) float s_fri[2][2][16];        // 256 B
    __shared__ __align__(16) float s_xi[2][2][12];         // 192 B
    __shared__ __align__(16) ll    s_jb[2][2*K_];          // 1024 B
    __shared__ __align__(16) float s_d[2][K_*NPAIR];       // 7168 B (per residue of pair)
    __shared__ __align__(16) float s_t[2][K_*4];           // 1024 B

    int tid  = threadIdx.x;
    int w    = tid >> 5, lane = tid & 31;

    int4 ve = ((const int4*)eidxv)[lane];
    int is64 = (__reduce_or_sync(0xffffffffu, ve.y | ve.w) == 0);

    // W staging once per block
    {
        const float4* src = (const float4*)g_wsym;
        float4* dst = (float4*)s_wsym;
        #pragma unroll
        for (int i = tid; i < NPAIR*HALF_/4; i += 256) dst[i] = src[i];
    }
    if (tid < 96)                ((float4*)s_wv)[tid]      = ((const float4*)g_wv)[tid];
    if (tid >= 96 && tid < 128)  ((float4*)s_bias)[tid-96] = ((const float4*)g_bias)[tid-96];

    // staging roles
    int kk_x = 0, part_x = 0, s2x = 0, kx = 0;
    if (tid < 192){ kk_x = tid/3; part_x = tid - kk_x*3; s2x = kk_x >> 5; kx = kk_x & 31; }
    int kk_t = tid - 192;            // 0..63 for tid>=192
    int s2t = kk_t >> 5, kt = kk_t & 31;

    // synchronous staging of pair qq into slot ss
    auto stage = [&](int qq, int ss){
        int rbase = 2*qq;
        int bb = rbase & ~(L_-1);
        if (tid < 192){
            int rr = rbase + s2x;
            ll j = is64 ? ((const ll*)eidxv)[rr*K_ + kx]
                        : (ll)((const int*)eidxv)[rr*K_ + kx];
            ((float4*)&s_xj[ss][s2x][kx*12])[part_x] = ((const float4*)X)[(bb+(int)j)*3 + part_x];
        } else {
            int rr = rbase + s2t;
            ll j = is64 ? ((const ll*)eidxv)[rr*K_ + kt]
                        : (ll)((const int*)eidxv)[rr*K_ + kt];
            ((float4*)&s_tj[ss][s2t][kt*4])[0] = ((const float4*)g_fr)[(size_t)(bb+(int)j)*4 + 3];
        }
        if (tid >= 64 && tid < 72){
            int i = tid - 64; int s2 = i >> 2, f = i & 3;
            ((float4*)s_fri[ss][s2])[f] = ((const float4*)g_fr)[(size_t)(rbase+s2)*4 + f];
        }
        if (tid >= 72 && tid < 78){
            int i = tid - 72; int s2 = i/3, p = i - s2*3;
            ((float4*)s_xi[ss][s2])[p] = ((const float4*)X)[(rbase+s2)*3 + p];
        }
    };

    // distance + t_ji for the pair staged in slot ss (both residues)
    auto dist = [&](int ss){
        if (lane < NPAIR){
            int m = c_pm[lane], n = c_pn[lane];
            bool mI = (m < 4), nI = (n < 4);
            #pragma unroll
            for (int s2 = 0; s2 < 2; s2++){
                float mx=0.f,my=0.f,mz=0.f, nx=0.f,ny=0.f,nz=0.f;
                if (mI){ mx=s_xi[ss][s2][m*3]; my=s_xi[ss][s2][m*3+1]; mz=s_xi[ss][s2][m*3+2]; }
                if (nI){ nx=s_xi[ss][s2][n*3]; ny=s_xi[ss][s2][n*3+1]; nz=s_xi[ss][s2][n*3+2]; }
                #pragma unroll
                for (int e = 0; e < 4; e++){
                    int k = w*4 + e;
                    const float* xj = &s_xj[ss][s2][k*12];
                    float ax = mI ? mx : xj[(m-4)*3+0];
                    float ay = mI ? my : xj[(m-4)*3+1];
                    float az = mI ? mz : xj[(m-4)*3+2];
                    float bx = nI ? nx : xj[(n-4)*3+0];
                    float by = nI ? ny : xj[(n-4)*3+1];
                    float bz = nI ? nz : xj[(n-4)*3+2];
                    float dx=ax-bx, dy=ay-by, dz=az-bz;
                    float dd2 = fmaf(dx,dx, fmaf(dy,dy, fmaf(dz,dz, EPSF)));
                    s_d[s2][k*NPAIR + lane] = __fsqrt_rn(dd2);
                }
            }
        } else {
            int k = w*4 + (lane - NPAIR);
            #pragma unroll
            for (int s2 = 0; s2 < 2; s2++){
                float4 f0 = ((const float4*)s_fri[ss][s2])[0];
                float4 f1 = ((const float4*)s_fri[ss][s2])[1];
                float4 f2 = ((const float4*)s_fri[ss][s2])[2];
                float4 f3 = ((const float4*)s_fri[ss][s2])[3];
                float4 tj = ((const float4*)&s_tj[ss][s2][k*4])[0];
                float dx = tj.x - f3.x, dy = tj.y - f3.y, dz = tj.z - f3.z;
                float t0 = fmaf(f0.z,dz, fmaf(f0.y,dy, f0.x*dx));
                float t1 = fmaf(f1.z,dz, fmaf(f1.y,dy, f1.x*dx));
                float t2 = fmaf(f2.z,dz, fmaf(f2.y,dy, f2.x*dx));
                ((float4*)&s_t[s2][k*4])[0] = make_float4(t0, t1, t2, 0.f);
            }
        }
    };

    // --- prologue: stage pair q0 (slot0); jb[0] <- idx(pair q0+G) ---
    int q0 = blockIdx.x;
    stage(q0, 0);
    if (tid < 64 && q0 + GRID_ < NP2){
        int s2 = tid >> 5, k = tid & 31;
        int rr = 2*(q0 + GRID_) + s2;
        s_jb[0][tid] = is64 ? ((const ll*)eidxv)[rr*K_ + k]
                            : (ll)((const int*)eidxv)[rr*K_ + k];
    }
    __syncthreads();

    int q = q0, b = 0;
    while (true){
        int qn = q + GRID_;
        bool hn = qn < NP2;

        // --- zero-register prefetch for pair qn via cp.async ---
        if (hn){
            int rbase = 2*qn;
            int bb = rbase & ~(L_-1);
            if (tid < 192){
                ll j = is64 ? s_jb[b][kk_x] : (ll)(*(const int*)&s_jb[b][kk_x]);
                cp16(sa(&s_xj[b^1][s2x][kx*12 + part_x*4]),
                     (const char*)X + ((size_t)(bb+(int)j)*12 + part_x*4)*4);
            } else {
                ll j = is64 ? s_jb[b][kk_t] : (ll)(*(const int*)&s_jb[b][kk_t]);
                cp16(sa(&s_tj[b^1][s2t][kt*4]),
                     (const char*)g_fr + ((size_t)(bb+(int)j)*16 + 12)*4);
            }
            if (tid >= 64 && tid < 72){
                int i = tid - 64; int s2 = i >> 2, f = i & 3;
                cp16(sa(&s_fri[b^1][s2][f*4]),
                     (const char*)g_fr + ((size_t)(rbase+s2)*16 + f*4)*4);
            }
            if (tid >= 72 && tid < 78){
                int i = tid - 72; int s2 = i/3, p = i - s2*3;
                cp16(sa(&s_xi[b^1][s2][p*4]),
                     (const char*)X + ((size_t)(rbase+s2)*12 + p*4)*4);
            }
            if (tid < 64 && qn + GRID_ < NP2){
                int s2 = tid >> 5, k = tid & 31;
                int rr = 2*(qn + GRID_) + s2;
                if (is64) cp8(sa(&s_jb[b^1][tid]),
                              (const char*)eidxv + ((size_t)rr*K_ + k)*8);
                else      cp4(sa(&s_jb[b^1][tid]),
                              (const char*)eidxv + ((size_t)rr*K_ + k)*4);
            }
            asm volatile("cp.async.commit_group;" ::: "memory");
        }

        // --- dist for current pair (slot b) ---
        dist(b);
        __syncthreads();

        // --- compute: warp w = edges w*4..w*4+3, 128 cols (4/lane), 2 residues ---
        {
            int eb  = w * 4;
            int col = lane * 4;

            // hA/hB[s2*4+e]: {c0,c1}/{c2,c3} accumulators for residue s2, edge e
            ull hA[8], hB[8];
            {
                float4 bq = *(const float4*)&s_bias[col];
                ull bA = pack2(bq.x, bq.y), bB = pack2(bq.z, bq.w);
                #pragma unroll
                for (int i = 0; i < 8; i++){ hA[i]=bA; hB[i]=bB; }
            }
            #pragma unroll 1
            for (int pp = 0; pp < NPAIR; pp += 4){
                float4 q0v = *(const float4*)&s_wsym[(pp+0)*HALF_ + col];
                float4 q1v = *(const float4*)&s_wsym[(pp+1)*HALF_ + col];
                float4 q2v = *(const float4*)&s_wsym[(pp+2)*HALF_ + col];
                float4 q3v = *(const float4*)&s_wsym[(pp+3)*HALF_ + col];
                ull W0a=pack2(q0v.x,q0v.y), W0b=pack2(q0v.z,q0v.w);
                ull W1a=pack2(q1v.x,q1v.y), W1b=pack2(q1v.z,q1v.w);
                ull W2a=pack2(q2v.x,q2v.y), W2b=pack2(q2v.z,q2v.w);
                ull W3a=pack2(q3v.x,q3v.y), W3b=pack2(q3v.z,q3v.w);
                #pragma unroll
                for (int s2 = 0; s2 < 2; s2++){
                    #pragma unroll
                    for (int e = 0; e < 4; e++){
                        int i = s2*4 + e;
                        float4 dq = *(const float4*)&s_d[s2][(eb+e)*NPAIR + pp];  // broadcast
                        ull d0=dup2(dq.x), d1=dup2(dq.y), d2=dup2(dq.z), d3=dup2(dq.w);
                        hA[i] = fma2(d0, W0a, hA[i]);  hB[i] = fma2(d0, W0b, hB[i]);
                        hA[i] = fma2(d1, W1a, hA[i]);  hB[i] = fma2(d1, W1b, hB[i]);
                        hA[i] = fma2(d2, W2a, hA[i]);  hB[i] = fma2(d2, W2b, hB[i]);
                        hA[i] = fma2(d3, W3a, hA[i]);  hB[i] = fma2(d3, W3b, hB[i]);
                    }
                }
            }

            float4 wv0 = *(const float4*)&s_wv[0*HALF_ + col];
            float4 wv1 = *(const float4*)&s_wv[1*HALF_ + col];
            float4 wv2 = *(const float4*)&s_wv[2*HALF_ + col];
            ull v0a=pack2(wv0.x,wv0.y), v0b=pack2(wv0.z,wv0.w);
            ull v1a=pack2(wv1.x,wv1.y), v1b=pack2(wv1.z,wv1.w);
            ull v2a=pack2(wv2.x,wv2.y), v2b=pack2(wv2.z,wv2.w);

            #pragma unroll
            for (int s2 = 0; s2 < 2; s2++){
                #pragma unroll
                for (int e = 0; e < 4; e++){
                    int i = s2*4 + e;
                    int k = eb + e;
                    float4 tq = *(const float4*)&s_t[s2][k*4];   // broadcast
                    ull t0d = dup2(tq.x), t1d = dup2(tq.y), t2d = dup2(tq.z);
                    ull hvA = fma2(t2d, v2a, fma2(t1d, v1a, mul2(t0d, v0a)));
                    ull hvB = fma2(t2d, v2b, fma2(t1d, v1b, mul2(t0d, v0b)));

                    float a0,a1,a2,a3, b0,b1,b2,b3;
                    unpack2(hvA, a0, a1);  unpack2(hvB, a2, a3);
                    unpack2(hA[i], b0, b1);  unpack2(hB[i], b2, b3);
                    float sa0,ca0,sa1,ca1,sa2,ca2,sa3,ca3;
                    float sb0,cb0,sb1,cb1,sb2,cb2,sb3,cb3;
                    __sincosf(a0,&sa0,&ca0); __sincosf(a1,&sa1,&ca1);
                    __sincosf(a2,&sa2,&ca2); __sincosf(a3,&sa3,&ca3);
                    __sincosf(b0,&sb0,&cb0); __sincosf(b1,&sb1,&cb1);
                    __sincosf(b2,&sb2,&cb2); __sincosf(b3,&sb3,&cb3);
                    size_t obase = ((size_t)((2*q + s2)*K_ + k))*256 + col;
                    __stcs((float4*)&out[obase],
                           make_float4(ca0+cb0, ca1+cb1, ca2+cb2, ca3+cb3));
                    __stcs((float4*)&out[obase + 128],
                           make_float4(sa0+sb0, sa1+sb1, sa2+sb2, sa3+sb3));
                }
            }
        }

        asm volatile("cp.async.wait_group 0;" ::: "memory");
        __syncthreads();
        if (!hn) break;
        q = qn; b ^= 1;
    }
}

// ---------------------------------------------------------------------------
extern "C" void kernel_launch(void* const* d_in, const int* in_sizes, int n_in,
                              void* d_out, int out_size){
    const float* X     = (const float*)d_in[0];
    const void*  eidx  = d_in[1];
    const void*  C     = d_in[2];
    const float* Wvec  = (const float*)d_in[3];
    const float* Wdist = (const float*)d_in[4];
    (void)in_sizes; (void)n_in; (void)out_size;

    prep_kernel<<<33, 256>>>(X, C, Wvec, Wdist);
    edge_kernel<<<GRID_, 256>>>(X, eidx, (float*)d_out);
}